// round 16
// baseline (speedup 1.0000x reference)
#include <cuda_runtime.h>
#include <cuda_bf16.h>
#include <cuda_fp16.h>
#include <cstdint>
#include <math.h>

#define BSZ   2048
#define NTOT  4096
#define DDIM  256
#define NT2   272            // tiles: sum_{bjc=0..15} (2*bjc+2)
#define OFF_B 32768          // [A_s0 16K][A_s1 16K][B_s0 32K][B_s1 32K]
#define SMEM_TOTAL 98304
#define NTHR  512
#define L2E2  2.885390081777927f      // 2*log2(e)
#define HM256 (L2E2 / 256.0f)         // logits carry a 256x scale (zn x16, squared)

// Scratch (device globals; no allocation allowed)
__device__ uint4  g_zn8[NTOT * DDIM / 16];   // normalized rows x16, e4m3
__device__ float  g_rowsum[NTOT];
__device__ float  g_pos[NTOT];
__device__ unsigned g_done = 0;

// ---------------------------------------------------------------------------
// Kernel 1: L2-normalize rows -> e4m3 (scaled x16); zero accumulators
// ---------------------------------------------------------------------------
__device__ __forceinline__ uint16_t f2x_e4m3(float lo, float hi) {
    uint16_t r;   // d = {hi, lo}: first source is the HIGH byte
    asm("cvt.rn.satfinite.e4m3x2.f32 %0, %1, %2;" : "=h"(r) : "f"(hi), "f"(lo));
    return r;
}

__global__ __launch_bounds__(256) void nt_normalize(const float* __restrict__ zi,
                                                    const float* __restrict__ zj) {
    int row  = (blockIdx.x * blockDim.x + threadIdx.x) >> 5;
    int lane = threadIdx.x & 31;
    if (blockIdx.x == 0 && threadIdx.x == 0) g_done = 0u;
    if (row >= NTOT) return;

    const float* src = (row < BSZ) ? (zi + (size_t)row * DDIM)
                                   : (zj + (size_t)(row - BSZ) * DDIM);
    const float4* s4 = (const float4*)src;
    float4 a = s4[lane];
    float4 b = s4[lane + 32];

    float ss = a.x*a.x + a.y*a.y + a.z*a.z + a.w*a.w
             + b.x*b.x + b.y*b.y + b.z*b.z + b.w*b.w;
#pragma unroll
    for (int o = 16; o; o >>= 1) ss += __shfl_xor_sync(0xFFFFFFFFu, ss, o);

    float inv = 16.0f / fmaxf(sqrtf(ss), 1e-8f);   // x16 scale into e4m3 range

    uint32_t* dst = (uint32_t*)g_zn8 + (size_t)row * 64;   // 256 B/row
    uint32_t w0 = (uint32_t)f2x_e4m3(a.x*inv, a.y*inv)
                | ((uint32_t)f2x_e4m3(a.z*inv, a.w*inv) << 16);
    uint32_t w1 = (uint32_t)f2x_e4m3(b.x*inv, b.y*inv)
                | ((uint32_t)f2x_e4m3(b.z*inv, b.w*inv) << 16);
    dst[lane]      = w0;
    dst[lane + 32] = w1;

    if (lane == 0) g_rowsum[row] = 0.0f;
}

// ---------------------------------------------------------------------------
// Helpers
// ---------------------------------------------------------------------------
__device__ __forceinline__ void cp_async16(uint32_t s, const void* g) {
    asm volatile("cp.async.cg.shared.global [%0], [%1], 16;\n" :: "r"(s), "l"(g));
}
__device__ __forceinline__ void cp_commit() { asm volatile("cp.async.commit_group;\n"); }
__device__ __forceinline__ void cp_wait0()  { asm volatile("cp.async.wait_group 0;\n"); }
__device__ __forceinline__ void ldm_x4(uint32_t addr, uint32_t& r0, uint32_t& r1,
                                       uint32_t& r2, uint32_t& r3) {
    asm volatile("ldmatrix.sync.aligned.m8n8.x4.shared.b16 {%0,%1,%2,%3}, [%4];\n"
                 : "=r"(r0), "=r"(r1), "=r"(r2), "=r"(r3) : "r"(addr));
}
// fp8 e4m3 inputs, f16 accumulators: m16n8k32 (2x MACs per instruction)
__device__ __forceinline__ void qmma(uint32_t& d0, uint32_t& d1,
                                     uint32_t a0, uint32_t a1, uint32_t a2, uint32_t a3,
                                     uint32_t b0, uint32_t b1) {
    asm volatile("mma.sync.aligned.m16n8k32.row.col.f16.e4m3.e4m3.f16 "
                 "{%0,%1}, {%2,%3,%4,%5}, {%6,%7}, {%0,%1};\n"
                 : "+r"(d0), "+r"(d1)
                 : "r"(a0), "r"(a1), "r"(a2), "r"(a3), "r"(b0), "r"(b1));
}
__device__ __forceinline__ uint32_t sw128(uint32_t off) {
    return off ^ ((off >> 3) & 0x70);
}
__device__ __forceinline__ float ex2f(float x) {
    float r;
    asm("ex2.approx.ftz.f32 %0, %1;" : "=f"(r) : "f"(x));
    return r;
}
__device__ __forceinline__ __half2 h2_ex2(__half2 x) {
    uint32_t xi = *reinterpret_cast<uint32_t*>(&x);
    uint32_t ri;
    asm("ex2.approx.f16x2 %0, %1;" : "=r"(ri) : "r"(xi));
    return *reinterpret_cast<__half2*>(&ri);
}

// ---------------------------------------------------------------------------
// Kernel 2: e4m3 mma.sync GEMM, 128x256 tiles over the upper triangle.
// Whole K=256 resident in smem (two 128B K-slabs per operand): ONE load,
// ONE barrier, 8 k32-steps. 512 threads (4m x 4n warps, warp tile 32x64),
// f16x2 accumulators. Warp-uniform skip/diag/pos specialization.
// ---------------------------------------------------------------------------
__global__ __launch_bounds__(NTHR, 2) void nt_mma(float* __restrict__ out) {
    extern __shared__ __align__(1024) char smem[];
    uint32_t sb;
    asm("{ .reg .u64 t; cvta.to.shared.u64 t, %1; cvt.u32.u64 %0, t; }"
        : "=r"(sb) : "l"((const void*)smem));

    // decode tile: for bjc in 0..15, bi in 0..2*bjc+1
    int t = blockIdx.x, bjc = 0;
    while (t >= 2 * bjc + 2) { t -= 2 * bjc + 2; bjc++; }
    const int bi = t;
    const int rowBase    = bi * 128;
    const int colBase256 = bjc * 256;

    const int tid  = threadIdx.x;
    const int wid  = tid >> 5;
    const int lane = tid & 31;
    const int warp_m = wid & 3;      // 32 rows each
    const int warp_n = wid >> 2;     // 64 cols each

    const int colBlock = 2 * bjc + (warp_n >> 1);
    const bool skipW = (colBlock < bi);
    const bool diagW = (colBlock == bi);
    const bool posW  = (colBlock == bi + 16);

    const char* Zb = (const char*)g_zn8;

    // ---- Single full-K load: A 2048 chunks (4/thr), B 4096 chunks (8/thr)
    {
        const int lr = tid >> 4;         // base row step 32 (A) / covers via loop
        const int c  = tid & 15;         // 16B chunk within 256B row
        const uint32_t slab = (uint32_t)(c >> 3);
        const uint32_t wsw  = sw128((uint32_t)((c & 7) * 16));  // within-row part
        // A: rows lr, lr+32, lr+64, lr+96
#pragma unroll
        for (int l = 0; l < 4; l++) {
            int r = lr + l * 32;
            uint32_t dst = sb + slab * 16384
                         + (sw128((uint32_t)(r * 128 + (c & 7) * 16)));
            cp_async16(dst, Zb + (size_t)(rowBase + r) * 256 + c * 16);
        }
        // B: rows lr, lr+32, ..., lr+224
#pragma unroll
        for (int l = 0; l < 8; l++) {
            int r = lr + l * 32;
            uint32_t dst = sb + OFF_B + slab * 32768
                         + (sw128((uint32_t)(r * 128 + (c & 7) * 16)));
            cp_async16(dst, Zb + (size_t)(colBase256 + r) * 256 + c * 16);
        }
        (void)wsw;
        cp_commit();
    }

    uint32_t acc[2][8][2];               // f16x2 accumulators (scaled dot)
#pragma unroll
    for (int mi = 0; mi < 2; mi++)
#pragma unroll
        for (int ni = 0; ni < 8; ni++) { acc[mi][ni][0] = 0u; acc[mi][ni][1] = 0u; }

    // ldmatrix bases (strength-reduced swizzle; verified rounds 13-15)
    const uint32_t c   = (uint32_t)(lane & 7) << 4;
    const uint32_t c4  = c & 0x10;
    const uint32_t c56 = c & 0x60;
    const uint32_t bA0 = sb
        + (uint32_t)((warp_m * 32 + (lane & 15)) * 128)
        + (((uint32_t)(lane >> 4) * 16) ^ c4);
    const uint32_t bB0 = sb + OFF_B
        + (uint32_t)((warp_n * 64 + (lane >> 4) * 8 + (lane & 7)) * 128)
        + ((((uint32_t)(lane >> 3) & 1) * 16) ^ c4);

    cp_wait0();
    __syncthreads();

    if (!skipW) {
#pragma unroll
        for (int slab = 0; slab < 2; slab++) {
            const uint32_t a0 = bA0 + (uint32_t)slab * 16384;
            const uint32_t b0 = bB0 + (uint32_t)slab * 32768;
#pragma unroll
            for (int ks = 0; ks < 4; ks++) {
                const uint32_t kk = ((uint32_t)ks * 32) ^ c56;
                uint32_t a[2][4];
                ldm_x4(a0 + kk,        a[0][0], a[0][1], a[0][2], a[0][3]);
                ldm_x4(a0 + 2048 + kk, a[1][0], a[1][1], a[1][2], a[1][3]);
#pragma unroll
                for (int p = 0; p < 4; p++) {
                    uint32_t b00, b01, b10, b11;
                    ldm_x4(b0 + (uint32_t)p * 2048 + kk, b00, b01, b10, b11);
#pragma unroll
                    for (int mi = 0; mi < 2; mi++) {
                        qmma(acc[mi][2*p][0],   acc[mi][2*p][1],
                             a[mi][0], a[mi][1], a[mi][2], a[mi][3], b00, b01);
                        qmma(acc[mi][2*p+1][0], acc[mi][2*p+1][1],
                             a[mi][0], a[mi][1], a[mi][2], a[mi][3], b10, b11);
                    }
                }
            }
        }

        // ---- Epilogue: dot_scaled = 256*cos; e = 2^(ds*L2E2/256 - L2E2) = exp(2cos-2)
        const int wc = colBase256 + warp_n * 64;
        const __half2 hM = __float2half2_rn(HM256);
        const __half2 hB = __float2half2_rn(-L2E2);
        __half2 colsum2[8];
#pragma unroll
        for (int ni = 0; ni < 8; ni++) colsum2[ni] = __float2half2_rn(0.0f);

#pragma unroll
        for (int mi = 0; mi < 2; mi++) {
#pragma unroll
            for (int half = 0; half < 2; half++) {
                int row = rowBase + warp_m * 32 + mi * 16 + half * 8 + (lane >> 2);
                __half2 e2[8];
#pragma unroll
                for (int ni = 0; ni < 8; ni++) {
                    __half2 av = *reinterpret_cast<__half2*>(&acc[mi][ni][half]);
                    e2[ni] = h2_ex2(__hfma2(av, hM, hB));
                    colsum2[ni] = __hadd2(colsum2[ni], e2[ni]);
                }
                __half2 t0 = __hadd2(__hadd2(e2[0], e2[1]), __hadd2(e2[2], e2[3]));
                __half2 t1 = __hadd2(__hadd2(e2[4], e2[5]), __hadd2(e2[6], e2[7]));
                float2 vf = __half22float2(__hadd2(t0, t1));
                float s = vf.x + vf.y;

                if (diagW) {
#pragma unroll
                    for (int ni = 0; ni < 8; ni++)
#pragma unroll
                        for (int cc = 0; cc < 2; cc++) {
                            int col = wc + ni * 8 + 2 * (lane & 3) + cc;
                            if (col == row) {
                                __half2 av = *reinterpret_cast<__half2*>(&acc[mi][ni][half]);
                                float v = cc ? __half2float(__high2half(av))
                                             : __half2float(__low2half(av));
                                s -= ex2f(fmaf(v, HM256, -L2E2));
                            }
                        }
                } else if (posW) {
#pragma unroll
                    for (int ni = 0; ni < 8; ni++)
#pragma unroll
                        for (int cc = 0; cc < 2; cc++) {
                            int col = wc + ni * 8 + 2 * (lane & 3) + cc;
                            if (col == row + BSZ) {
                                __half2 av = *reinterpret_cast<__half2*>(&acc[mi][ni][half]);
                                float v = (1.0f / 128.0f) *
                                    (cc ? __half2float(__high2half(av))
                                        : __half2float(__low2half(av)));
                                g_pos[row] = v; g_pos[col] = v;
                            }
                        }
                }
                s += __shfl_xor_sync(0xFFFFFFFFu, s, 1);
                s += __shfl_xor_sync(0xFFFFFFFFu, s, 2);
                if ((lane & 3) == 0) atomicAdd(&g_rowsum[row], s);
            }
        }

        if (!diagW) {
#pragma unroll
            for (int ni = 0; ni < 8; ni++) {
                float2 cf = __half22float2(colsum2[ni]);
#pragma unroll
                for (int cc = 0; cc < 2; cc++) {
                    float s = cc ? cf.y : cf.x;
                    s += __shfl_xor_sync(0xFFFFFFFFu, s, 4);
                    s += __shfl_xor_sync(0xFFFFFFFFu, s, 8);
                    s += __shfl_xor_sync(0xFFFFFFFFu, s, 16);
                    if (lane < 4) {
                        int col = wc + ni * 8 + 2 * lane + cc;
                        atomicAdd(&g_rowsum[col], s);
                    }
                }
            }
        }
    }

    // ---- last-CTA finalize
    __threadfence();
    __syncthreads();
    __shared__ unsigned s_last;
    if (tid == 0) s_last = (atomicAdd(&g_done, 1u) == NT2 - 1) ? 1u : 0u;
    __syncthreads();
    if (s_last) {
        __shared__ float red[NTHR];
        float s = 0.0f;
        for (int i = tid; i < NTOT; i += NTHR)
            s += 2.0f + __logf(__ldcg(&g_rowsum[i])) - __ldcg(&g_pos[i]);
        red[tid] = s;
        __syncthreads();
#pragma unroll
        for (int o = NTHR / 2; o; o >>= 1) {
            if (tid < o) red[tid] += red[tid + o];
            __syncthreads();
        }
        if (tid == 0) out[0] = red[0] * (1.0f / NTOT);
    }
}

extern "C" void kernel_launch(void* const* d_in, const int* in_sizes, int n_in,
                              void* d_out, int out_size) {
    const float* zi = (const float*)d_in[0];
    const float* zj = (const float*)d_in[1];
    float* out = (float*)d_out;
    (void)in_sizes; (void)n_in; (void)out_size;

    cudaFuncSetAttribute(nt_mma, cudaFuncAttributeMaxDynamicSharedMemorySize, SMEM_TOTAL);

    nt_normalize<<<NTOT / 8, 256>>>(zi, zj);
    nt_mma<<<NT2, NTHR, SMEM_TOTAL>>>(out);
}